// round 1
// baseline (speedup 1.0000x reference)
#include <cuda_runtime.h>
#include <cstdint>

#define D 128
#define N_NODES_MAX 100000

// 51.2 MB scratch for support = x @ W (allocation-free rule: __device__ global)
__device__ float g_support[(size_t)N_NODES_MAX * D];

// ---------------------------------------------------------------------------
// Kernel 1: out[r][d] = bias[d]  (vectorized float4)
// ---------------------------------------------------------------------------
__global__ void init_out_kernel(float4* __restrict__ out4,
                                const float4* __restrict__ bias4,
                                size_t total4) {
    size_t i = (size_t)blockIdx.x * blockDim.x + threadIdx.x;
    size_t stride = (size_t)gridDim.x * blockDim.x;
    for (; i < total4; i += stride) {
        out4[i] = bias4[i & 31];   // 128 floats = 32 float4 per row
    }
}

// ---------------------------------------------------------------------------
// Kernel 2: support = x @ W   (M x 128 @ 128 x 128, fp32)
// Tile: BM=64 rows, BN=128 cols, BK=32. 256 threads, each computes 4x8.
// ---------------------------------------------------------------------------
#define BM 64
#define BN 128
#define BK 32

__global__ __launch_bounds__(256, 2)
void gemm_kernel(const float* __restrict__ x,
                 const float* __restrict__ w,
                 float* __restrict__ sup,
                 int n_rows) {
    __shared__ float Xs[BM][BK + 1];   // +1 pad: kill bank conflicts on row-varying reads
    __shared__ float Ws[BK][BN];

    const int tid = threadIdx.x;
    const int block_row = blockIdx.x * BM;
    const int ty = tid >> 4;   // 0..15 -> 4 rows each
    const int tx = tid & 15;   // 0..15 -> 8 cols each

    float acc[4][8];
#pragma unroll
    for (int i = 0; i < 4; i++)
#pragma unroll
        for (int j = 0; j < 8; j++) acc[i][j] = 0.f;

    for (int k0 = 0; k0 < D; k0 += BK) {
        // Load X tile: 64x32 = 2048 elems, 8 per thread, coalesced over k
#pragma unroll
        for (int i = 0; i < 8; i++) {
            int e = tid + i * 256;
            int r = e >> 5, kk = e & 31;
            int gr = block_row + r;
            Xs[r][kk] = (gr < n_rows) ? x[(size_t)gr * D + k0 + kk] : 0.f;
        }
        // Load W tile: 32x128 = 4096 elems, 16 per thread, coalesced over n
#pragma unroll
        for (int i = 0; i < 16; i++) {
            int e = tid + i * 256;
            int kk = e >> 7, n = e & 127;
            Ws[kk][n] = w[(size_t)(k0 + kk) * D + n];
        }
        __syncthreads();

#pragma unroll
        for (int kk = 0; kk < BK; kk++) {
            float a[4];
#pragma unroll
            for (int i = 0; i < 4; i++) a[i] = Xs[ty * 4 + i][kk];
            float4 b0 = *(const float4*)&Ws[kk][tx * 8];
            float4 b1 = *(const float4*)&Ws[kk][tx * 8 + 4];
            float b[8] = {b0.x, b0.y, b0.z, b0.w, b1.x, b1.y, b1.z, b1.w};
#pragma unroll
            for (int i = 0; i < 4; i++)
#pragma unroll
                for (int j = 0; j < 8; j++)
                    acc[i][j] = fmaf(a[i], b[j], acc[i][j]);
        }
        __syncthreads();
    }

    // Write 4x8 per thread as two float4 per row
#pragma unroll
    for (int i = 0; i < 4; i++) {
        int gr = block_row + ty * 4 + i;
        if (gr < n_rows) {
            float4* dst = (float4*)&sup[(size_t)gr * D + tx * 8];
            dst[0] = make_float4(acc[i][0], acc[i][1], acc[i][2], acc[i][3]);
            dst[1] = make_float4(acc[i][4], acc[i][5], acc[i][6], acc[i][7]);
        }
    }
}

// ---------------------------------------------------------------------------
// Kernel 3: scatter — one warp per edge.
//   out[row] += val * support[col]   via red.global.add.v4.f32
// ---------------------------------------------------------------------------
__global__ void scatter_kernel(const int* __restrict__ erow,
                               const int* __restrict__ ecol,
                               const float* __restrict__ eval_,
                               const float* __restrict__ sup,
                               float* __restrict__ out,
                               int n_edges) {
    const int lane = threadIdx.x & 31;
    int warp = (int)((blockIdx.x * (size_t)blockDim.x + threadIdx.x) >> 5);
    const int total_warps = (int)(((size_t)gridDim.x * blockDim.x) >> 5);

    for (int e = warp; e < n_edges; e += total_warps) {
        int r = 0, c = 0;
        float v = 0.f;
        if (lane == 0) {
            r = erow[e];
            c = ecol[e];
            v = eval_[e];
        }
        r = __shfl_sync(0xFFFFFFFFu, r, 0);
        c = __shfl_sync(0xFFFFFFFFu, c, 0);
        v = __shfl_sync(0xFFFFFFFFu, v, 0);

        float4 s = *(const float4*)&sup[(size_t)c * D + lane * 4];
        float* dst = &out[(size_t)r * D + lane * 4];
        asm volatile("red.global.add.v4.f32 [%0], {%1, %2, %3, %4};"
                     :: "l"(dst), "f"(s.x * v), "f"(s.y * v),
                        "f"(s.z * v), "f"(s.w * v)
                     : "memory");
    }
}

// ---------------------------------------------------------------------------
// Launch
// Inputs (metadata order): x [N,128] f32, weight [128,128] f32, bias [128] f32,
//   edge_row [E] i32, edge_col [E] i32, edge_vals [E] f32
// Output: [N,128] f32
// ---------------------------------------------------------------------------
extern "C" void kernel_launch(void* const* d_in, const int* in_sizes, int n_in,
                              void* d_out, int out_size) {
    const float* x      = (const float*)d_in[0];
    const float* weight = (const float*)d_in[1];
    const float* bias   = (const float*)d_in[2];
    const int*   erow   = (const int*)d_in[3];
    const int*   ecol   = (const int*)d_in[4];
    const float* evals  = (const float*)d_in[5];
    float* out = (float*)d_out;

    const int n_rows  = in_sizes[0] / D;
    const int n_edges = in_sizes[3];

    float* sup = nullptr;
    cudaGetSymbolAddress((void**)&sup, g_support);

    // 1) out = bias (broadcast per row)
    {
        size_t total4 = (size_t)out_size / 4;
        int threads = 256;
        int blocks = 2048;
        init_out_kernel<<<blocks, threads>>>((float4*)out, (const float4*)bias,
                                             total4);
    }

    // 2) support = x @ W
    {
        int blocks = (n_rows + BM - 1) / BM;
        gemm_kernel<<<blocks, 256>>>(x, weight, sup, n_rows);
    }

    // 3) scatter-accumulate edges
    {
        int threads = 256;                       // 8 warps / block
        int blocks = (n_edges + 7) / 8;          // one warp per edge
        scatter_kernel<<<blocks, threads>>>(erow, ecol, evals, sup, out,
                                            n_edges);
    }
}

// round 2
// speedup vs baseline: 1.5076x; 1.5076x over previous
#include <cuda_runtime.h>
#include <cstdint>

#define D 128
#define N_NODES_MAX 100000
#define N_EDGES_MAX 3200000

// Static scratch (allocation-free rule: __device__ globals)
__device__ float g_support[(size_t)N_NODES_MAX * D];        // 51.2 MB
__device__ int   g_count[N_NODES_MAX];                      // histogram
__device__ int   g_offs[N_NODES_MAX + 1];                   // CSR row offsets
__device__ int   g_cursor[N_NODES_MAX];                     // scatter cursors
__device__ int2  g_sorted[N_EDGES_MAX];                     // packed (col, val)

// ---------------------------------------------------------------------------
// Kernel 0: zero the histogram
// ---------------------------------------------------------------------------
__global__ void zero_kernel(int* __restrict__ cnt, int n) {
    int i = blockIdx.x * blockDim.x + threadIdx.x;
    if (i < n) cnt[i] = 0;
}

// ---------------------------------------------------------------------------
// Kernel 1: histogram of edge_row
// ---------------------------------------------------------------------------
__global__ void hist_kernel(const int* __restrict__ erow,
                            int* __restrict__ cnt, int n_edges) {
    int i = blockIdx.x * blockDim.x + threadIdx.x;
    int stride = gridDim.x * blockDim.x;
    for (; i < n_edges; i += stride) {
        atomicAdd(&cnt[erow[i]], 1);   // compiles to RED (no return)
    }
}

// ---------------------------------------------------------------------------
// Kernel 2: exclusive scan (single block, 1024 threads, warp-scan based)
// Writes offs[0..n] and cursor[0..n-1].
// ---------------------------------------------------------------------------
__global__ __launch_bounds__(1024, 1)
void scan_kernel(const int* __restrict__ cnt,
                 int* __restrict__ offs,
                 int* __restrict__ cursor, int n) {
    __shared__ int wsum[32];
    __shared__ int carry;
    const int tid = threadIdx.x;
    const int lane = tid & 31;
    const int wid = tid >> 5;

    if (tid == 0) carry = 0;
    __syncthreads();

    for (int base = 0; base < n; base += 1024) {
        int i = base + tid;
        int v = (i < n) ? cnt[i] : 0;

        // warp inclusive scan
        int incl = v;
#pragma unroll
        for (int d = 1; d < 32; d <<= 1) {
            int t = __shfl_up_sync(0xFFFFFFFFu, incl, d);
            if (lane >= d) incl += t;
        }
        if (lane == 31) wsum[wid] = incl;
        __syncthreads();

        // warp 0 turns wsum into exclusive warp prefixes
        if (wid == 0) {
            int w = wsum[lane];
            int s = w;
#pragma unroll
            for (int d = 1; d < 32; d <<= 1) {
                int t = __shfl_up_sync(0xFFFFFFFFu, s, d);
                if (lane >= d) s += t;
            }
            wsum[lane] = s - w;   // exclusive
        }
        __syncthreads();

        int excl = carry + wsum[wid] + (incl - v);
        if (i < n) { offs[i] = excl; cursor[i] = excl; }
        __syncthreads();
        if (tid == 1023) carry += wsum[31] + incl;   // block total
        __syncthreads();
    }
    if (tid == 0) offs[n] = carry;
}

// ---------------------------------------------------------------------------
// Kernel 3: bin-scatter edges into CSR order, packed (col, val_bits)
// ---------------------------------------------------------------------------
__global__ void binscatter_kernel(const int* __restrict__ erow,
                                  const int* __restrict__ ecol,
                                  const float* __restrict__ evals,
                                  int* __restrict__ cursor,
                                  int2* __restrict__ sorted, int n_edges) {
    int i = blockIdx.x * blockDim.x + threadIdx.x;
    int stride = gridDim.x * blockDim.x;
    for (; i < n_edges; i += stride) {
        int r = erow[i];
        int pos = atomicAdd(&cursor[r], 1);
        sorted[pos] = make_int2(ecol[i], __float_as_int(evals[i]));
    }
}

// ---------------------------------------------------------------------------
// Kernel 4: support = x @ W   (M x 128 @ 128 x 128, fp32)  — unchanged
// ---------------------------------------------------------------------------
#define BM 64
#define BN 128
#define BK 32

__global__ __launch_bounds__(256, 2)
void gemm_kernel(const float* __restrict__ x,
                 const float* __restrict__ w,
                 float* __restrict__ sup,
                 int n_rows) {
    __shared__ float Xs[BM][BK + 1];
    __shared__ float Ws[BK][BN];

    const int tid = threadIdx.x;
    const int block_row = blockIdx.x * BM;
    const int ty = tid >> 4;
    const int tx = tid & 15;

    float acc[4][8];
#pragma unroll
    for (int i = 0; i < 4; i++)
#pragma unroll
        for (int j = 0; j < 8; j++) acc[i][j] = 0.f;

    for (int k0 = 0; k0 < D; k0 += BK) {
#pragma unroll
        for (int i = 0; i < 8; i++) {
            int e = tid + i * 256;
            int r = e >> 5, kk = e & 31;
            int gr = block_row + r;
            Xs[r][kk] = (gr < n_rows) ? x[(size_t)gr * D + k0 + kk] : 0.f;
        }
#pragma unroll
        for (int i = 0; i < 16; i++) {
            int e = tid + i * 256;
            int kk = e >> 7, n = e & 127;
            Ws[kk][n] = w[(size_t)(k0 + kk) * D + n];
        }
        __syncthreads();

#pragma unroll
        for (int kk = 0; kk < BK; kk++) {
            float a[4];
#pragma unroll
            for (int i = 0; i < 4; i++) a[i] = Xs[ty * 4 + i][kk];
            float4 b0 = *(const float4*)&Ws[kk][tx * 8];
            float4 b1 = *(const float4*)&Ws[kk][tx * 8 + 4];
            float b[8] = {b0.x, b0.y, b0.z, b0.w, b1.x, b1.y, b1.z, b1.w};
#pragma unroll
            for (int i = 0; i < 4; i++)
#pragma unroll
                for (int j = 0; j < 8; j++)
                    acc[i][j] = fmaf(a[i], b[j], acc[i][j]);
        }
        __syncthreads();
    }

#pragma unroll
    for (int i = 0; i < 4; i++) {
        int gr = block_row + ty * 4 + i;
        if (gr < n_rows) {
            float4* dst = (float4*)&sup[(size_t)gr * D + tx * 8];
            dst[0] = make_float4(acc[i][0], acc[i][1], acc[i][2], acc[i][3]);
            dst[1] = make_float4(acc[i][4], acc[i][5], acc[i][6], acc[i][7]);
        }
    }
}

// ---------------------------------------------------------------------------
// Kernel 5: gather — one warp per row.
//   out[r] = bias + sum_{e in row r} val_e * support[col_e]
// No atomics; accumulate in registers, single streaming write.
// ---------------------------------------------------------------------------
__global__ __launch_bounds__(256)
void gather_kernel(const int* __restrict__ offs,
                   const int2* __restrict__ sorted,
                   const float* __restrict__ sup,
                   const float* __restrict__ bias,
                   float* __restrict__ out, int n_rows) {
    __shared__ int2 stage[8][32];   // 8 warps per 256-thread block
    const int lane = threadIdx.x & 31;
    const int wloc = threadIdx.x >> 5;
    int warp = (int)((blockIdx.x * (size_t)blockDim.x + threadIdx.x) >> 5);
    const int nwarps = (int)(((size_t)gridDim.x * blockDim.x) >> 5);

    const float4 b = ((const float4*)bias)[lane];

    for (int r = warp; r < n_rows; r += nwarps) {
        const int s = offs[r];
        const int e = offs[r + 1];
        float4 acc = make_float4(0.f, 0.f, 0.f, 0.f);

        for (int base = s; base < e; base += 32) {
            int idx = base + lane;
            int2 ed = (idx < e) ? sorted[idx] : make_int2(0, 0);
            stage[wloc][lane] = ed;
            __syncwarp();
            const int m = min(32, e - base);
            int k = 0;
            // 4-way unrolled: 4 independent LDG.128 in flight per warp
            for (; k + 4 <= m; k += 4) {
                int2 e0 = stage[wloc][k];
                int2 e1 = stage[wloc][k + 1];
                int2 e2 = stage[wloc][k + 2];
                int2 e3 = stage[wloc][k + 3];
                float4 s0 = ((const float4*)(sup + (size_t)e0.x * D))[lane];
                float4 s1 = ((const float4*)(sup + (size_t)e1.x * D))[lane];
                float4 s2 = ((const float4*)(sup + (size_t)e2.x * D))[lane];
                float4 s3 = ((const float4*)(sup + (size_t)e3.x * D))[lane];
                float v0 = __int_as_float(e0.y);
                float v1 = __int_as_float(e1.y);
                float v2 = __int_as_float(e2.y);
                float v3 = __int_as_float(e3.y);
                acc.x = fmaf(v0, s0.x, acc.x); acc.y = fmaf(v0, s0.y, acc.y);
                acc.z = fmaf(v0, s0.z, acc.z); acc.w = fmaf(v0, s0.w, acc.w);
                acc.x = fmaf(v1, s1.x, acc.x); acc.y = fmaf(v1, s1.y, acc.y);
                acc.z = fmaf(v1, s1.z, acc.z); acc.w = fmaf(v1, s1.w, acc.w);
                acc.x = fmaf(v2, s2.x, acc.x); acc.y = fmaf(v2, s2.y, acc.y);
                acc.z = fmaf(v2, s2.z, acc.z); acc.w = fmaf(v2, s2.w, acc.w);
                acc.x = fmaf(v3, s3.x, acc.x); acc.y = fmaf(v3, s3.y, acc.y);
                acc.z = fmaf(v3, s3.z, acc.z); acc.w = fmaf(v3, s3.w, acc.w);
            }
            for (; k < m; k++) {
                int2 ek = stage[wloc][k];
                float4 sk = ((const float4*)(sup + (size_t)ek.x * D))[lane];
                float v = __int_as_float(ek.y);
                acc.x = fmaf(v, sk.x, acc.x); acc.y = fmaf(v, sk.y, acc.y);
                acc.z = fmaf(v, sk.z, acc.z); acc.w = fmaf(v, sk.w, acc.w);
            }
            __syncwarp();
        }

        float4 res = make_float4(acc.x + b.x, acc.y + b.y,
                                 acc.z + b.z, acc.w + b.w);
        ((float4*)(out + (size_t)r * D))[lane] = res;
    }
}

// ---------------------------------------------------------------------------
// Launch
// Inputs: x [N,128] f32, weight [128,128] f32, bias [128] f32,
//   edge_row [E] i32, edge_col [E] i32, edge_vals [E] f32
// Output: [N,128] f32
// ---------------------------------------------------------------------------
extern "C" void kernel_launch(void* const* d_in, const int* in_sizes, int n_in,
                              void* d_out, int out_size) {
    const float* x      = (const float*)d_in[0];
    const float* weight = (const float*)d_in[1];
    const float* bias   = (const float*)d_in[2];
    const int*   erow   = (const int*)d_in[3];
    const int*   ecol   = (const int*)d_in[4];
    const float* evals  = (const float*)d_in[5];
    float* out = (float*)d_out;

    const int n_rows  = in_sizes[0] / D;
    const int n_edges = in_sizes[3];

    float* sup;   cudaGetSymbolAddress((void**)&sup,   g_support);
    int*   cnt;   cudaGetSymbolAddress((void**)&cnt,   g_count);
    int*   offs;  cudaGetSymbolAddress((void**)&offs,  g_offs);
    int*   curs;  cudaGetSymbolAddress((void**)&curs,  g_cursor);
    int2*  srt;   cudaGetSymbolAddress((void**)&srt,   g_sorted);

    // CSR build
    zero_kernel<<<(n_rows + 255) / 256, 256>>>(cnt, n_rows);
    hist_kernel<<<1024, 256>>>(erow, cnt, n_edges);
    scan_kernel<<<1, 1024>>>(cnt, offs, curs, n_rows);
    binscatter_kernel<<<2048, 256>>>(erow, ecol, evals, curs, srt, n_edges);

    // Dense GEMM: support = x @ W
    gemm_kernel<<<(n_rows + BM - 1) / BM, 256>>>(x, weight, sup, n_rows);

    // Row-gather aggregation + bias (writes every output row exactly once)
    gather_kernel<<<(n_rows + 7) / 8, 256>>>(offs, srt, sup, bias, out, n_rows);
}

// round 3
// speedup vs baseline: 1.6583x; 1.0999x over previous
#include <cuda_runtime.h>
#include <cuda_fp16.h>
#include <cstdint>

#define D 128
#define N_NODES_MAX 100000
#define N_EDGES_MAX 3200000

// Static scratch (allocation-free rule: __device__ globals)
__device__ __half g_support[(size_t)N_NODES_MAX * D];       // 25.6 MB (fp16)
__device__ int    g_count[N_NODES_MAX];                     // histogram
__device__ int    g_offs[N_NODES_MAX + 1];                  // CSR row offsets
__device__ int    g_cursor[N_NODES_MAX];                    // scatter cursors
__device__ int2   g_sorted[N_EDGES_MAX];                    // packed (col, val)

// ---------------------------------------------------------------------------
// Kernel 0: zero the histogram
// ---------------------------------------------------------------------------
__global__ void zero_kernel(int* __restrict__ cnt, int n) {
    int i = blockIdx.x * blockDim.x + threadIdx.x;
    if (i < n) cnt[i] = 0;
}

// ---------------------------------------------------------------------------
// Kernel 1: histogram of edge_row
// ---------------------------------------------------------------------------
__global__ void hist_kernel(const int* __restrict__ erow,
                            int* __restrict__ cnt, int n_edges) {
    int i = blockIdx.x * blockDim.x + threadIdx.x;
    int stride = gridDim.x * blockDim.x;
    for (; i < n_edges; i += stride) {
        atomicAdd(&cnt[erow[i]], 1);   // RED (no return)
    }
}

// ---------------------------------------------------------------------------
// Kernel 2: exclusive scan (single block, 1024 threads)
// ---------------------------------------------------------------------------
__global__ __launch_bounds__(1024, 1)
void scan_kernel(const int* __restrict__ cnt,
                 int* __restrict__ offs,
                 int* __restrict__ cursor, int n) {
    __shared__ int wsum[32];
    __shared__ int carry;
    const int tid = threadIdx.x;
    const int lane = tid & 31;
    const int wid = tid >> 5;

    if (tid == 0) carry = 0;
    __syncthreads();

    for (int base = 0; base < n; base += 1024) {
        int i = base + tid;
        int v = (i < n) ? cnt[i] : 0;

        int incl = v;
#pragma unroll
        for (int d = 1; d < 32; d <<= 1) {
            int t = __shfl_up_sync(0xFFFFFFFFu, incl, d);
            if (lane >= d) incl += t;
        }
        if (lane == 31) wsum[wid] = incl;
        __syncthreads();

        if (wid == 0) {
            int w = wsum[lane];
            int s = w;
#pragma unroll
            for (int d = 1; d < 32; d <<= 1) {
                int t = __shfl_up_sync(0xFFFFFFFFu, s, d);
                if (lane >= d) s += t;
            }
            wsum[lane] = s - w;
        }
        __syncthreads();

        int excl = carry + wsum[wid] + (incl - v);
        if (i < n) { offs[i] = excl; cursor[i] = excl; }
        __syncthreads();
        if (tid == 1023) carry += wsum[31] + incl;
        __syncthreads();
    }
    if (tid == 0) offs[n] = carry;
}

// ---------------------------------------------------------------------------
// Kernel 3: bin-scatter, 4-way unrolled for atomic MLP
// ---------------------------------------------------------------------------
__global__ void binscatter_kernel(const int* __restrict__ erow,
                                  const int* __restrict__ ecol,
                                  const float* __restrict__ evals,
                                  int* __restrict__ cursor,
                                  int2* __restrict__ sorted, int n_edges) {
    const int tid = blockIdx.x * blockDim.x + threadIdx.x;
    const int T = gridDim.x * blockDim.x;

    int i = tid;
    for (; i + 3 * T < n_edges; i += 4 * T) {
        int i0 = i, i1 = i + T, i2 = i + 2 * T, i3 = i + 3 * T;
        int r0 = erow[i0], r1 = erow[i1], r2 = erow[i2], r3 = erow[i3];
        int c0 = ecol[i0], c1 = ecol[i1], c2 = ecol[i2], c3 = ecol[i3];
        float v0 = evals[i0], v1 = evals[i1], v2 = evals[i2], v3 = evals[i3];
        // 4 independent atomics in flight
        int p0 = atomicAdd(&cursor[r0], 1);
        int p1 = atomicAdd(&cursor[r1], 1);
        int p2 = atomicAdd(&cursor[r2], 1);
        int p3 = atomicAdd(&cursor[r3], 1);
        sorted[p0] = make_int2(c0, __float_as_int(v0));
        sorted[p1] = make_int2(c1, __float_as_int(v1));
        sorted[p2] = make_int2(c2, __float_as_int(v2));
        sorted[p3] = make_int2(c3, __float_as_int(v3));
    }
    for (; i < n_edges; i += T) {
        int r = erow[i];
        int pos = atomicAdd(&cursor[r], 1);
        sorted[pos] = make_int2(ecol[i], __float_as_int(evals[i]));
    }
}

// ---------------------------------------------------------------------------
// Kernel 4: support = x @ W  (fp32 accumulate, fp16 store)
// ---------------------------------------------------------------------------
#define BM 64
#define BN 128
#define BK 32

__global__ __launch_bounds__(256, 2)
void gemm_kernel(const float* __restrict__ x,
                 const float* __restrict__ w,
                 __half* __restrict__ sup,
                 int n_rows) {
    __shared__ float Xs[BM][BK + 1];
    __shared__ float Ws[BK][BN];

    const int tid = threadIdx.x;
    const int block_row = blockIdx.x * BM;
    const int ty = tid >> 4;
    const int tx = tid & 15;

    float acc[4][8];
#pragma unroll
    for (int i = 0; i < 4; i++)
#pragma unroll
        for (int j = 0; j < 8; j++) acc[i][j] = 0.f;

    for (int k0 = 0; k0 < D; k0 += BK) {
#pragma unroll
        for (int i = 0; i < 8; i++) {
            int e = tid + i * 256;
            int r = e >> 5, kk = e & 31;
            int gr = block_row + r;
            Xs[r][kk] = (gr < n_rows) ? x[(size_t)gr * D + k0 + kk] : 0.f;
        }
#pragma unroll
        for (int i = 0; i < 16; i++) {
            int e = tid + i * 256;
            int kk = e >> 7, n = e & 127;
            Ws[kk][n] = w[(size_t)(k0 + kk) * D + n];
        }
        __syncthreads();

#pragma unroll
        for (int kk = 0; kk < BK; kk++) {
            float a[4];
#pragma unroll
            for (int i = 0; i < 4; i++) a[i] = Xs[ty * 4 + i][kk];
            float4 b0 = *(const float4*)&Ws[kk][tx * 8];
            float4 b1 = *(const float4*)&Ws[kk][tx * 8 + 4];
            float b[8] = {b0.x, b0.y, b0.z, b0.w, b1.x, b1.y, b1.z, b1.w};
#pragma unroll
            for (int i = 0; i < 4; i++)
#pragma unroll
                for (int j = 0; j < 8; j++)
                    acc[i][j] = fmaf(a[i], b[j], acc[i][j]);
        }
        __syncthreads();
    }

    // Convert 8 floats -> 8 halves, one 16B store per row-slice
#pragma unroll
    for (int i = 0; i < 4; i++) {
        int gr = block_row + ty * 4 + i;
        if (gr < n_rows) {
            __half2 h[4];
#pragma unroll
            for (int j = 0; j < 4; j++)
                h[j] = __floats2half2_rn(acc[i][2 * j], acc[i][2 * j + 1]);
            *(uint4*)&sup[(size_t)gr * D + tx * 8] = *(uint4*)h;
        }
    }
}

// ---------------------------------------------------------------------------
// Kernel 5: gather — one warp per row. fp16 support, fp32 accumulate.
//   out[r] = bias + sum_{e in row r} val_e * support[col_e]
// ---------------------------------------------------------------------------
__global__ __launch_bounds__(256)
void gather_kernel(const int* __restrict__ offs,
                   const int2* __restrict__ sorted,
                   const __half* __restrict__ sup,
                   const float* __restrict__ bias,
                   float* __restrict__ out, int n_rows) {
    __shared__ int2 stage[8][32];
    const int lane = threadIdx.x & 31;
    const int wloc = threadIdx.x >> 5;
    int warp = (int)((blockIdx.x * (size_t)blockDim.x + threadIdx.x) >> 5);
    const int nwarps = (int)(((size_t)gridDim.x * blockDim.x) >> 5);

    const float4 b = ((const float4*)bias)[lane];

    for (int r = warp; r < n_rows; r += nwarps) {
        const int s = offs[r];
        const int e = offs[r + 1];
        float4 acc = make_float4(0.f, 0.f, 0.f, 0.f);

        for (int base = s; base < e; base += 32) {
            int idx = base + lane;
            int2 ed = (idx < e) ? sorted[idx] : make_int2(0, 0);
            stage[wloc][lane] = ed;
            __syncwarp();
            const int m = min(32, e - base);
            int k = 0;
            for (; k + 4 <= m; k += 4) {
                int2 e0 = stage[wloc][k];
                int2 e1 = stage[wloc][k + 1];
                int2 e2 = stage[wloc][k + 2];
                int2 e3 = stage[wloc][k + 3];
                // 4 independent LDG.64: lane's 4 halves of each support row
                uint2 u0 = ((const uint2*)(sup + (size_t)e0.x * D))[lane];
                uint2 u1 = ((const uint2*)(sup + (size_t)e1.x * D))[lane];
                uint2 u2 = ((const uint2*)(sup + (size_t)e2.x * D))[lane];
                uint2 u3 = ((const uint2*)(sup + (size_t)e3.x * D))[lane];
                float v0 = __int_as_float(e0.y);
                float v1 = __int_as_float(e1.y);
                float v2 = __int_as_float(e2.y);
                float v3 = __int_as_float(e3.y);
                {
                    float2 lo = __half22float2(*(__half2*)&u0.x);
                    float2 hi = __half22float2(*(__half2*)&u0.y);
                    acc.x = fmaf(v0, lo.x, acc.x); acc.y = fmaf(v0, lo.y, acc.y);
                    acc.z = fmaf(v0, hi.x, acc.z); acc.w = fmaf(v0, hi.y, acc.w);
                }
                {
                    float2 lo = __half22float2(*(__half2*)&u1.x);
                    float2 hi = __half22float2(*(__half2*)&u1.y);
                    acc.x = fmaf(v1, lo.x, acc.x); acc.y = fmaf(v1, lo.y, acc.y);
                    acc.z = fmaf(v1, hi.x, acc.z); acc.w = fmaf(v1, hi.y, acc.w);
                }
                {
                    float2 lo = __half22float2(*(__half2*)&u2.x);
                    float2 hi = __half22float2(*(__half2*)&u2.y);
                    acc.x = fmaf(v2, lo.x, acc.x); acc.y = fmaf(v2, lo.y, acc.y);
                    acc.z = fmaf(v2, hi.x, acc.z); acc.w = fmaf(v2, hi.y, acc.w);
                }
                {
                    float2 lo = __half22float2(*(__half2*)&u3.x);
                    float2 hi = __half22float2(*(__half2*)&u3.y);
                    acc.x = fmaf(v3, lo.x, acc.x); acc.y = fmaf(v3, lo.y, acc.y);
                    acc.z = fmaf(v3, hi.x, acc.z); acc.w = fmaf(v3, hi.y, acc.w);
                }
            }
            for (; k < m; k++) {
                int2 ek = stage[wloc][k];
                uint2 u = ((const uint2*)(sup + (size_t)ek.x * D))[lane];
                float v = __int_as_float(ek.y);
                float2 lo = __half22float2(*(__half2*)&u.x);
                float2 hi = __half22float2(*(__half2*)&u.y);
                acc.x = fmaf(v, lo.x, acc.x); acc.y = fmaf(v, lo.y, acc.y);
                acc.z = fmaf(v, hi.x, acc.z); acc.w = fmaf(v, hi.y, acc.w);
            }
            __syncwarp();
        }

        float4 res = make_float4(acc.x + b.x, acc.y + b.y,
                                 acc.z + b.z, acc.w + b.w);
        ((float4*)(out + (size_t)r * D))[lane] = res;
    }
}

// ---------------------------------------------------------------------------
// Launch
// ---------------------------------------------------------------------------
extern "C" void kernel_launch(void* const* d_in, const int* in_sizes, int n_in,
                              void* d_out, int out_size) {
    const float* x      = (const float*)d_in[0];
    const float* weight = (const float*)d_in[1];
    const float* bias   = (const float*)d_in[2];
    const int*   erow   = (const int*)d_in[3];
    const int*   ecol   = (const int*)d_in[4];
    const float* evals  = (const float*)d_in[5];
    float* out = (float*)d_out;

    const int n_rows  = in_sizes[0] / D;
    const int n_edges = in_sizes[3];

    __half* sup;  cudaGetSymbolAddress((void**)&sup,  g_support);
    int*    cnt;  cudaGetSymbolAddress((void**)&cnt,  g_count);
    int*    offs; cudaGetSymbolAddress((void**)&offs, g_offs);
    int*    curs; cudaGetSymbolAddress((void**)&curs, g_cursor);
    int2*   srt;  cudaGetSymbolAddress((void**)&srt,  g_sorted);

    // CSR build
    zero_kernel<<<(n_rows + 255) / 256, 256>>>(cnt, n_rows);
    hist_kernel<<<1024, 256>>>(erow, cnt, n_edges);
    scan_kernel<<<1, 1024>>>(cnt, offs, curs, n_rows);
    binscatter_kernel<<<2048, 256>>>(erow, ecol, evals, curs, srt, n_edges);

    // Dense GEMM: support = x @ W  (fp16 out)
    gemm_kernel<<<(n_rows + BM - 1) / BM, 256>>>(x, weight, sup, n_rows);

    // Row-gather aggregation + bias
    gather_kernel<<<(n_rows + 7) / 8, 256>>>(offs, srt, sup, bias, out, n_rows);
}

// round 4
// speedup vs baseline: 2.2143x; 1.3353x over previous
#include <cuda_runtime.h>
#include <cuda_fp16.h>
#include <mma.h>
#include <cstdint>

using namespace nvcuda;

#define D 128
#define N_NODES_MAX 100000
#define N_EDGES_MAX 3200000

// Static scratch (allocation-free rule: __device__ globals)
__device__ __half g_support[(size_t)N_NODES_MAX * D];       // 25.6 MB (fp16)
__device__ int    g_count[N_NODES_MAX];
__device__ int    g_offs[N_NODES_MAX + 1];
__device__ int    g_cursor[N_NODES_MAX];
__device__ int2   g_sorted[N_EDGES_MAX];

// ---------------------------------------------------------------------------
// Kernel 0: zero the histogram
// ---------------------------------------------------------------------------
__global__ void zero_kernel(int* __restrict__ cnt, int n) {
    int i = blockIdx.x * blockDim.x + threadIdx.x;
    if (i < n) cnt[i] = 0;
}

// ---------------------------------------------------------------------------
// Kernel 1: histogram of edge_row — int4 vectorized, 4 REDs per thread
// ---------------------------------------------------------------------------
__global__ void hist_kernel(const int* __restrict__ erow,
                            int* __restrict__ cnt, int n_edges) {
    int i = blockIdx.x * blockDim.x + threadIdx.x;
    int n4 = n_edges >> 2;
    if (i < n4) {
        int4 r = ((const int4*)erow)[i];
        atomicAdd(&cnt[r.x], 1);
        atomicAdd(&cnt[r.y], 1);
        atomicAdd(&cnt[r.z], 1);
        atomicAdd(&cnt[r.w], 1);
    }
    // tail
    int t = n4 * 4 + i;
    if (i < (n_edges & 3)) atomicAdd(&cnt[erow[n4 * 4 + i]], 1);
    (void)t;
}

// ---------------------------------------------------------------------------
// Kernel 2: exclusive scan (single block, 1024 threads)
// ---------------------------------------------------------------------------
__global__ __launch_bounds__(1024, 1)
void scan_kernel(const int* __restrict__ cnt,
                 int* __restrict__ offs,
                 int* __restrict__ cursor, int n) {
    __shared__ int wsum[32];
    __shared__ int carry;
    const int tid = threadIdx.x;
    const int lane = tid & 31;
    const int wid = tid >> 5;

    if (tid == 0) carry = 0;
    __syncthreads();

    for (int base = 0; base < n; base += 1024) {
        int i = base + tid;
        int v = (i < n) ? cnt[i] : 0;

        int incl = v;
#pragma unroll
        for (int d = 1; d < 32; d <<= 1) {
            int t = __shfl_up_sync(0xFFFFFFFFu, incl, d);
            if (lane >= d) incl += t;
        }
        if (lane == 31) wsum[wid] = incl;
        __syncthreads();

        if (wid == 0) {
            int w = wsum[lane];
            int s = w;
#pragma unroll
            for (int d = 1; d < 32; d <<= 1) {
                int t = __shfl_up_sync(0xFFFFFFFFu, s, d);
                if (lane >= d) s += t;
            }
            wsum[lane] = s - w;
        }
        __syncthreads();

        int excl = carry + wsum[wid] + (incl - v);
        if (i < n) { offs[i] = excl; cursor[i] = excl; }
        __syncthreads();
        if (tid == 1023) carry += wsum[31] + incl;
        __syncthreads();
    }
    if (tid == 0) offs[n] = carry;
}

// ---------------------------------------------------------------------------
// Kernel 3: bin-scatter — 8 contiguous edges per thread, int4 loads,
// 8 atomics in flight (MLP=8).
// ---------------------------------------------------------------------------
__global__ void binscatter_kernel(const int* __restrict__ erow,
                                  const int* __restrict__ ecol,
                                  const float* __restrict__ evals,
                                  int* __restrict__ cursor,
                                  int2* __restrict__ sorted, int n_edges) {
    const int g = blockIdx.x * blockDim.x + threadIdx.x;
    const int base = g * 8;
    if (base + 8 <= n_edges) {
        int4 r0 = ((const int4*)erow)[g * 2];
        int4 r1 = ((const int4*)erow)[g * 2 + 1];
        int4 c0 = ((const int4*)ecol)[g * 2];
        int4 c1 = ((const int4*)ecol)[g * 2 + 1];
        float4 v0 = ((const float4*)evals)[g * 2];
        float4 v1 = ((const float4*)evals)[g * 2 + 1];
        int p0 = atomicAdd(&cursor[r0.x], 1);
        int p1 = atomicAdd(&cursor[r0.y], 1);
        int p2 = atomicAdd(&cursor[r0.z], 1);
        int p3 = atomicAdd(&cursor[r0.w], 1);
        int p4 = atomicAdd(&cursor[r1.x], 1);
        int p5 = atomicAdd(&cursor[r1.y], 1);
        int p6 = atomicAdd(&cursor[r1.z], 1);
        int p7 = atomicAdd(&cursor[r1.w], 1);
        sorted[p0] = make_int2(c0.x, __float_as_int(v0.x));
        sorted[p1] = make_int2(c0.y, __float_as_int(v0.y));
        sorted[p2] = make_int2(c0.z, __float_as_int(v0.z));
        sorted[p3] = make_int2(c0.w, __float_as_int(v0.w));
        sorted[p4] = make_int2(c1.x, __float_as_int(v1.x));
        sorted[p5] = make_int2(c1.y, __float_as_int(v1.y));
        sorted[p6] = make_int2(c1.z, __float_as_int(v1.z));
        sorted[p7] = make_int2(c1.w, __float_as_int(v1.w));
    } else if (base < n_edges) {
        for (int i = base; i < n_edges; i++) {
            int pos = atomicAdd(&cursor[erow[i]], 1);
            sorted[pos] = make_int2(ecol[i], __float_as_int(evals[i]));
        }
    }
}

// ---------------------------------------------------------------------------
// Kernel 4: WMMA tensor-core GEMM: support = half(x @ W)
//   64x128 tile per block, 256 threads = 8 warps (4 warp_m x 2 warp_n).
//   x, W converted to fp16 in smem; fp32 accumulate; fp16 store.
// Dynamic smem layout (52224 B):
//   half Wh[128][136]  (34816 B)   | after mma, region reused as
//   half Xh[64][136]   (17408 B)   | float stage[64][128] (32768 B)
// ---------------------------------------------------------------------------
#define LDW 136
#define SMEM_W_BYTES (128 * LDW * 2)
#define GEMM_SMEM_BYTES (SMEM_W_BYTES + 64 * LDW * 2)

__global__ __launch_bounds__(256)
void wmma_gemm_kernel(const float* __restrict__ x,
                      const float* __restrict__ w,
                      __half* __restrict__ sup, int n_rows) {
    extern __shared__ char smem[];
    __half* Wh = (__half*)smem;
    __half* Xh = (__half*)(smem + SMEM_W_BYTES);
    float*  stage = (float*)smem;

    const int tid = threadIdx.x;
    const int block_row = blockIdx.x * 64;

    // Load W (128x128 f32 -> f16), 4 elems per iter
    for (int i = tid; i < 128 * 128 / 4; i += 256) {
        int r = (i * 4) >> 7;
        int c = (i * 4) & 127;
        float4 f = ((const float4*)w)[i];
        __half2 h[2] = { __floats2half2_rn(f.x, f.y),
                         __floats2half2_rn(f.z, f.w) };
        *(uint2*)&Wh[r * LDW + c] = *(uint2*)h;
    }
    // Load X tile (64x128 f32 -> f16), zero-pad OOB rows
    for (int i = tid; i < 64 * 128 / 4; i += 256) {
        int r = (i * 4) >> 7;
        int c = (i * 4) & 127;
        int gr = block_row + r;
        float4 f = make_float4(0.f, 0.f, 0.f, 0.f);
        if (gr < n_rows) f = ((const float4*)x)[gr * 32 + (c >> 2)];
        __half2 h[2] = { __floats2half2_rn(f.x, f.y),
                         __floats2half2_rn(f.z, f.w) };
        *(uint2*)&Xh[r * LDW + c] = *(uint2*)h;
    }
    __syncthreads();

    const int wid = tid >> 5;
    const int wm = wid & 3;    // 0..3 -> 16 rows each
    const int wn = wid >> 2;   // 0..1 -> 64 cols each

    wmma::fragment<wmma::accumulator, 16, 16, 16, float> acc[4];
#pragma unroll
    for (int j = 0; j < 4; j++) wmma::fill_fragment(acc[j], 0.f);

#pragma unroll
    for (int k = 0; k < 128; k += 16) {
        wmma::fragment<wmma::matrix_a, 16, 16, 16, __half, wmma::row_major> a;
        wmma::load_matrix_sync(a, &Xh[(wm * 16) * LDW + k], LDW);
#pragma unroll
        for (int j = 0; j < 4; j++) {
            wmma::fragment<wmma::matrix_b, 16, 16, 16, __half, wmma::row_major> b;
            wmma::load_matrix_sync(b, &Wh[k * LDW + wn * 64 + j * 16], LDW);
            wmma::mma_sync(acc[j], a, b, acc[j]);
        }
    }

    __syncthreads();   // all reads of Xh/Wh done before reuse as stage
#pragma unroll
    for (int j = 0; j < 4; j++)
        wmma::store_matrix_sync(&stage[(wm * 16) * 128 + wn * 64 + j * 16],
                                acc[j], 128, wmma::mem_row_major);
    __syncthreads();

    // Convert stage f32 -> f16, coalesced 16B stores
    for (int i = tid; i < 64 * 128 / 8; i += 256) {
        int r = (i * 8) >> 7;
        int c = (i * 8) & 127;
        int gr = block_row + r;
        if (gr < n_rows) {
            float4 f0 = *(float4*)&stage[r * 128 + c];
            float4 f1 = *(float4*)&stage[r * 128 + c + 4];
            __half2 h[4] = { __floats2half2_rn(f0.x, f0.y),
                             __floats2half2_rn(f0.z, f0.w),
                             __floats2half2_rn(f1.x, f1.y),
                             __floats2half2_rn(f1.z, f1.w) };
            *(uint4*)&sup[(size_t)gr * D + c] = *(uint4*)h;
        }
    }
}

// ---------------------------------------------------------------------------
// Kernel 5: gather — one warp per row. fp16 support, fp32 accumulate.
// ---------------------------------------------------------------------------
__global__ __launch_bounds__(256)
void gather_kernel(const int* __restrict__ offs,
                   const int2* __restrict__ sorted,
                   const __half* __restrict__ sup,
                   const float* __restrict__ bias,
                   float* __restrict__ out, int n_rows) {
    __shared__ int2 stage[8][32];
    const int lane = threadIdx.x & 31;
    const int wloc = threadIdx.x >> 5;
    int warp = (int)((blockIdx.x * (size_t)blockDim.x + threadIdx.x) >> 5);
    const int nwarps = (int)(((size_t)gridDim.x * blockDim.x) >> 5);

    const float4 b = ((const float4*)bias)[lane];

    for (int r = warp; r < n_rows; r += nwarps) {
        const int s = offs[r];
        const int e = offs[r + 1];
        float4 acc = make_float4(0.f, 0.f, 0.f, 0.f);

        for (int base = s; base < e; base += 32) {
            int idx = base + lane;
            int2 ed = (idx < e) ? sorted[idx] : make_int2(0, 0);
            stage[wloc][lane] = ed;
            __syncwarp();
            const int m = min(32, e - base);
            int k = 0;
            for (; k + 4 <= m; k += 4) {
                int2 e0 = stage[wloc][k];
                int2 e1 = stage[wloc][k + 1];
                int2 e2 = stage[wloc][k + 2];
                int2 e3 = stage[wloc][k + 3];
                uint2 u0 = ((const uint2*)(sup + (size_t)e0.x * D))[lane];
                uint2 u1 = ((const uint2*)(sup + (size_t)e1.x * D))[lane];
                uint2 u2 = ((const uint2*)(sup + (size_t)e2.x * D))[lane];
                uint2 u3 = ((const uint2*)(sup + (size_t)e3.x * D))[lane];
                float v0 = __int_as_float(e0.y);
                float v1 = __int_as_float(e1.y);
                float v2 = __int_as_float(e2.y);
                float v3 = __int_as_float(e3.y);
                {
                    float2 lo = __half22float2(*(__half2*)&u0.x);
                    float2 hi = __half22float2(*(__half2*)&u0.y);
                    acc.x = fmaf(v0, lo.x, acc.x); acc.y = fmaf(v0, lo.y, acc.y);
                    acc.z = fmaf(v0, hi.x, acc.z); acc.w = fmaf(v0, hi.y, acc.w);
                }
                {
                    float2 lo = __half22float2(*(__half2*)&u1.x);
                    float2 hi = __half22float2(*(__half2*)&u1.y);
                    acc.x = fmaf(v1, lo.x, acc.x); acc.y = fmaf(v1, lo.y, acc.y);
                    acc.z = fmaf(v1, hi.x, acc.z); acc.w = fmaf(v1, hi.y, acc.w);
                }
                {
                    float2 lo = __half22float2(*(__half2*)&u2.x);
                    float2 hi = __half22float2(*(__half2*)&u2.y);
                    acc.x = fmaf(v2, lo.x, acc.x); acc.y = fmaf(v2, lo.y, acc.y);
                    acc.z = fmaf(v2, hi.x, acc.z); acc.w = fmaf(v2, hi.y, acc.w);
                }
                {
                    float2 lo = __half22float2(*(__half2*)&u3.x);
                    float2 hi = __half22float2(*(__half2*)&u3.y);
                    acc.x = fmaf(v3, lo.x, acc.x); acc.y = fmaf(v3, lo.y, acc.y);
                    acc.z = fmaf(v3, hi.x, acc.z); acc.w = fmaf(v3, hi.y, acc.w);
                }
            }
            for (; k < m; k++) {
                int2 ek = stage[wloc][k];
                uint2 u = ((const uint2*)(sup + (size_t)ek.x * D))[lane];
                float v = __int_as_float(ek.y);
                float2 lo = __half22float2(*(__half2*)&u.x);
                float2 hi = __half22float2(*(__half2*)&u.y);
                acc.x = fmaf(v, lo.x, acc.x); acc.y = fmaf(v, lo.y, acc.y);
                acc.z = fmaf(v, hi.x, acc.z); acc.w = fmaf(v, hi.y, acc.w);
            }
            __syncwarp();
        }

        float4 res = make_float4(acc.x + b.x, acc.y + b.y,
                                 acc.z + b.z, acc.w + b.w);
        ((float4*)(out + (size_t)r * D))[lane] = res;
    }
}

// ---------------------------------------------------------------------------
// Launch
// ---------------------------------------------------------------------------
extern "C" void kernel_launch(void* const* d_in, const int* in_sizes, int n_in,
                              void* d_out, int out_size) {
    const float* x      = (const float*)d_in[0];
    const float* weight = (const float*)d_in[1];
    const float* bias   = (const float*)d_in[2];
    const int*   erow   = (const int*)d_in[3];
    const int*   ecol   = (const int*)d_in[4];
    const float* evals  = (const float*)d_in[5];
    float* out = (float*)d_out;

    const int n_rows  = in_sizes[0] / D;
    const int n_edges = in_sizes[3];

    __half* sup;  cudaGetSymbolAddress((void**)&sup,  g_support);
    int*    cnt;  cudaGetSymbolAddress((void**)&cnt,  g_count);
    int*    offs; cudaGetSymbolAddress((void**)&offs, g_offs);
    int*    curs; cudaGetSymbolAddress((void**)&curs, g_cursor);
    int2*   srt;  cudaGetSymbolAddress((void**)&srt,  g_sorted);

    // CSR build
    zero_kernel<<<(n_rows + 255) / 256, 256>>>(cnt, n_rows);
    {
        int n4 = (n_edges + 3) / 4;
        hist_kernel<<<(n4 + 255) / 256, 256>>>(erow, cnt, n_edges);
    }
    scan_kernel<<<1, 1024>>>(cnt, offs, curs, n_rows);
    {
        int groups = (n_edges + 7) / 8;
        binscatter_kernel<<<(groups + 255) / 256, 256>>>(erow, ecol, evals,
                                                         curs, srt, n_edges);
    }

    // Tensor-core GEMM: support = x @ W (fp16 out)
    static bool attr_set = false;
    if (!attr_set) {
        cudaFuncSetAttribute(wmma_gemm_kernel,
                             cudaFuncAttributeMaxDynamicSharedMemorySize,
                             GEMM_SMEM_BYTES);
        attr_set = true;
    }
    wmma_gemm_kernel<<<(n_rows + 63) / 64, 256, GEMM_SMEM_BYTES>>>(x, weight,
                                                                   sup, n_rows);

    // Row-gather aggregation + bias
    gather_kernel<<<(n_rows + 7) / 8, 256>>>(offs, srt, sup, bias, out, n_rows);
}